// round 10
// baseline (speedup 1.0000x reference)
#include <cuda_runtime.h>

// ---------------------------------------------------------------------------
// MambaSSM: B=2, L=384, d_inner=384, d_state=384, dt_rank=384, d_conv=4
//
//   gemm_splitk phase0 (grid 12,12,3): DTp[z]   = x @ dt_w^T (K-chunk z, raw)
//                                      XDBLp[z] = x @ B_w^T
//   gemm_splitk phase1 (grid 12,12,3): BMp[z] = (ΣXDBLp) @ B_w^T  (A summed at load)
//                                      CMp[z] = (ΣXDBLp) @ C_w^T
//   fuse_kernel: BM = ΣBMp ; CM = ΣCMp ;
//                dt = softplus(ΣDTp + dt_b); u = silu(conv(x)+cb);
//                g_SC[b][d][l] = (dt, dt*u, u*D[d], 0)
//   scan v5 (proven): CTA = 2 channels x 192 float2-lanes, deferred 2-lvl shfl.
// ---------------------------------------------------------------------------

#define LOG2E 1.4426950408889634f

__device__ float  g_DTp  [3][768 * 384];
__device__ float  g_XDBLp[3][768 * 384];
__device__ float  g_BMp  [3][768 * 384];
__device__ float  g_CMp  [3][768 * 384];
__device__ float  g_BM   [768 * 384];
__device__ float  g_CM   [768 * 384];
__device__ float4 g_SC   [768 * 384];   // (dt, dt*u, u*D, 0)

__device__ __forceinline__ float ex2f(float x) {
    float y;
    asm("ex2.approx.ftz.f32 %0, %1;" : "=f"(y) : "f"(x));
    return y;
}

// ---------------------------------------------------------------------------
// Split-K dual-output SGEMM: 64x64 tile, K-chunk = 128 (8 k-tiles of 16).
// grid (12, 12, 3); z = K-chunk. Raw partial outputs (no activation).
// ---------------------------------------------------------------------------
__global__ __launch_bounds__(256) void gemm_splitk(
    const float* __restrict__ x,
    const float* __restrict__ Wa,
    const float* __restrict__ Wb,
    int phase)
{
    __shared__ float As[16][64];
    __shared__ float Bs[16][64];

    const int tid = threadIdx.x;
    const int m0  = blockIdx.x * 64;
    const int bn  = blockIdx.y;            // 0..11
    const int z   = blockIdx.z;            // 0..2
    const int k0  = z * 128;
    const bool second = (bn >= 6);
    const float* W = second ? Wb : Wa;
    float* Cc = (phase == 0) ? (second ? g_XDBLp[z] : g_DTp[z])
                             : (second ? g_CMp[z]   : g_BMp[z]);
    const int n0 = (second ? bn - 6 : bn) * 64;

    const int loadRow = tid >> 2;          // 0..63
    const int loadCol = (tid & 3) << 2;    // 0,4,8,12
    const int aoff = (m0 + loadRow) * 384 + k0 + loadCol;
    const float* Wp = W + (n0 + loadRow) * 384 + k0 + loadCol;

    float4 aR;
    if (phase == 0) {
        aR = *(const float4*)(x + aoff);
    } else {
        const float4 p0 = *(const float4*)(g_XDBLp[0] + aoff);
        const float4 p1 = *(const float4*)(g_XDBLp[1] + aoff);
        const float4 p2 = *(const float4*)(g_XDBLp[2] + aoff);
        aR = make_float4(p0.x + p1.x + p2.x, p0.y + p1.y + p2.y,
                         p0.z + p1.z + p2.z, p0.w + p1.w + p2.w);
    }
    float4 wR = *(const float4*)Wp;

    float acc[4][4];
#pragma unroll
    for (int i = 0; i < 4; i++)
#pragma unroll
        for (int j = 0; j < 4; j++) acc[i][j] = 0.f;

    const int tx = tid & 15;
    const int ty = tid >> 4;

    for (int kt = 0; kt < 8; ++kt) {
        As[loadCol + 0][loadRow] = aR.x;
        As[loadCol + 1][loadRow] = aR.y;
        As[loadCol + 2][loadRow] = aR.z;
        As[loadCol + 3][loadRow] = aR.w;
        Bs[loadCol + 0][loadRow] = wR.x;
        Bs[loadCol + 1][loadRow] = wR.y;
        Bs[loadCol + 2][loadRow] = wR.z;
        Bs[loadCol + 3][loadRow] = wR.w;
        __syncthreads();

        if (kt < 7) {
            const int off = (kt + 1) * 16;
            if (phase == 0) {
                aR = *(const float4*)(x + aoff + off);
            } else {
                const float4 p0 = *(const float4*)(g_XDBLp[0] + aoff + off);
                const float4 p1 = *(const float4*)(g_XDBLp[1] + aoff + off);
                const float4 p2 = *(const float4*)(g_XDBLp[2] + aoff + off);
                aR = make_float4(p0.x + p1.x + p2.x, p0.y + p1.y + p2.y,
                                 p0.z + p1.z + p2.z, p0.w + p1.w + p2.w);
            }
            wR = *(const float4*)(Wp + off);
        }

#pragma unroll
        for (int k = 0; k < 16; ++k) {
            float4 av = *(const float4*)&As[k][ty << 2];
            float4 bv = *(const float4*)&Bs[k][tx << 2];
            float a[4] = {av.x, av.y, av.z, av.w};
            float b[4] = {bv.x, bv.y, bv.z, bv.w};
#pragma unroll
            for (int i = 0; i < 4; i++)
#pragma unroll
                for (int j = 0; j < 4; j++)
                    acc[i][j] = fmaf(a[i], b[j], acc[i][j]);
        }
        __syncthreads();
    }

#pragma unroll
    for (int i = 0; i < 4; i++) {
        const int m = m0 + (ty << 2) + i;
#pragma unroll
        for (int j = 0; j < 4; j++) {
            const int n = n0 + (tx << 2) + j;
            Cc[m * 384 + n] = acc[i][j];
        }
    }
}

// ---------------------------------------------------------------------------
// fuse: combine split-K parts (BM, CM), dt=softplus(sum+bias),
//       conv+silu, pack g_SC. grid (24, 2), block 384 (thread = channel d).
// ---------------------------------------------------------------------------
__global__ __launch_bounds__(384) void fuse_kernel(
    const float* __restrict__ x,
    const float* __restrict__ dt_b,
    const float* __restrict__ convw,
    const float* __restrict__ convb,
    const float* __restrict__ Dvec)
{
    const int d  = threadIdx.x;
    const int b  = blockIdx.y;
    const int l0 = blockIdx.x * 16;

    const float c0 = convw[d * 4 + 0];
    const float c1 = convw[d * 4 + 1];
    const float c2 = convw[d * 4 + 2];
    const float c3 = convw[d * 4 + 3];
    const float cb = convb[d];
    const float Dd = Dvec[d];
    const float bias = dt_b[d];

    const float* xb = x + b * 147456 + d;
    float4* scp = g_SC + (b * 384 + d) * 384;

    float w0 = (l0 - 3 >= 0) ? xb[(l0 - 3) * 384] : 0.f;
    float w1 = (l0 - 2 >= 0) ? xb[(l0 - 2) * 384] : 0.f;
    float w2 = (l0 - 1 >= 0) ? xb[(l0 - 1) * 384] : 0.f;

    for (int i = 0; i < 16; ++i) {
        const int l = l0 + i;
        const int m = b * 384 + l;
        const float w3 = xb[l * 384];
        float v = fmaf(w0, c0, fmaf(w1, c1, fmaf(w2, c2, fmaf(w3, c3, cb))));
        const float u = v / (1.f + expf(-v));              // silu

        // dt = softplus(sum of parts + bias)
        const int idt = m * 384 + d;
        float pre = g_DTp[0][idt] + g_DTp[1][idt] + g_DTp[2][idt] + bias;
        const float dt = fmaxf(pre, 0.f) + log1pf(expf(-fabsf(pre)));

        scp[l] = make_float4(dt, dt * u, u * Dd, 0.f);

        // combine BM / CM for row m, col d (coalesced across threads)
        g_BM[idt] = g_BMp[0][idt] + g_BMp[1][idt] + g_BMp[2][idt];
        g_CM[idt] = g_CMp[0][idt] + g_CMp[1][idt] + g_CMp[2][idt];

        w0 = w1; w1 = w2; w2 = w3;
    }
}

// ---------------------------------------------------------------------------
// SCAN v5 (proven): grid 384, block 384. CTA = 2 channels of one batch.
// ---------------------------------------------------------------------------
#define TL 48   // l-tile between smem reductions (384/48 = 8 tiles)

__global__ __launch_bounds__(384) void scan_kernel(
    const float* __restrict__ A_log,
    float* __restrict__ out)
{
    __shared__ float  part[2][TL][49];     // [ch][l_in_tile][48 partials + pad]
    __shared__ float4 scbuf[2][2][TL];     // [buf][ch][l_in_tile]

    const int tid  = threadIdx.x;
    const int lane = tid & 31;
    const int ch   = tid >= 192;
    const int s2   = tid - ch * 192;        // float2-state index 0..191
    const int wid6 = (tid >> 5) - ch * 6;   // warp index within channel 0..5

    const int pid   = blockIdx.x;           // 0..383
    const int b     = pid / 192;
    const int dbase = (pid - b * 192) * 2;
    const int d     = dbase + ch;

    // Per-thread invariants
    const float2 a = ((const float2*)(A_log + d * 384))[s2];
    const float A2x = -ex2f(a.x * LOG2E) * LOG2E;
    const float A2y = -ex2f(a.y * LOG2E) * LOG2E;
    const float2 bm = ((const float2*)(g_BM + (b * 384 + d) * 384))[s2];
    float hx = 0.f, hy = 0.f;

    const float4* scp0 = g_SC + (b * 384 + dbase) * 384;   // channel-0 stream
    const float2* Cb2  = (const float2*)(g_CM + b * 147456) + s2;

    // Preload tile 0 sc (threads 0..95: c = tid/48, li = tid%48)
    if (tid < 96) {
        const int c = tid / TL, li = tid - c * TL;
        scbuf[0][c][li] = __ldg(scp0 + c * 384 + li);
    }
    // Prefetch C rows l=0,1
    float2 C0 = __ldg(Cb2);
    float2 C1 = __ldg(Cb2 + 192);
    __syncthreads();

    float accP = 0.f;

    for (int tile = 0; tile < 8; ++tile) {
        const int lbase = tile * TL;
        const int buf   = tile & 1;

#pragma unroll 6
        for (int i = 0; i < TL; ++i) {
            const int l = lbase + i;
            const float4 sc = scbuf[buf][ch][i];   // LDS broadcast
            const float2 Cv = C0;
            C0 = C1;
            const int lpf = (l + 2 < 384) ? (l + 2) : 383;
            C1 = __ldg(Cb2 + lpf * 192);

            const float e0 = ex2f(sc.x * A2x);
            hx = fmaf(e0, hx, sc.y * bm.x);
            const float e1 = ex2f(sc.x * A2y);
            hy = fmaf(e1, hy, sc.y * bm.y);
            const float acc = fmaf(hy, Cv.y, hx * Cv.x);

            if (i > 0) {   // deferred: reduce previous iteration's partial
                accP += __shfl_xor_sync(0xffffffffu, accP, 16);
                accP += __shfl_xor_sync(0xffffffffu, accP, 8);
                if (lane < 8) part[ch][i - 1][wid6 * 8 + lane] = accP;
            }
            accP = acc;
        }
        // flush last iteration of the tile
        accP += __shfl_xor_sync(0xffffffffu, accP, 16);
        accP += __shfl_xor_sync(0xffffffffu, accP, 8);
        if (lane < 8) part[ch][TL - 1][wid6 * 8 + lane] = accP;
        __syncthreads();

        // Reduce + write out (tid<96); load next tile's sc (tid 96..191)
        if (tid < 96) {
            const int c  = tid / TL;
            const int li = tid - c * TL;
            const float* p = part[c][li];
            float t0 = 0.f, t1 = 0.f, t2 = 0.f, t3 = 0.f;
#pragma unroll
            for (int j = 0; j < 48; j += 4) {
                t0 += p[j]; t1 += p[j + 1]; t2 += p[j + 2]; t3 += p[j + 3];
            }
            const int l = lbase + li;
            float y = (t0 + t1) + (t2 + t3);
            y += scbuf[buf][c][li].z;              // u*D term
            out[(size_t)b * 147456 + (size_t)l * 384 + dbase + c] = y;
        } else if (tid < 192 && tile < 7) {
            const int t2i = tid - 96;
            const int c = t2i / TL, li = t2i - c * TL;
            scbuf[buf ^ 1][c][li] = __ldg(scp0 + c * 384 + lbase + TL + li);
        }
        __syncthreads();
    }
}

// ---------------------------------------------------------------------------
extern "C" void kernel_launch(void* const* d_in, const int* in_sizes, int n_in,
                              void* d_out, int out_size)
{
    const float* x      = (const float*)d_in[0];
    const float* A_log  = (const float*)d_in[1];
    const float* Dvec   = (const float*)d_in[2];
    const float* dt_w   = (const float*)d_in[3];
    const float* dt_b   = (const float*)d_in[4];
    const float* B_w    = (const float*)d_in[5];
    const float* C_w    = (const float*)d_in[6];
    const float* conv_w = (const float*)d_in[7];
    const float* conv_b = (const float*)d_in[8];
    float* out = (float*)d_out;

    // GEMM1 split-K: DTp (raw) + XDBLp
    gemm_splitk<<<dim3(12, 12, 3), 256>>>(x, dt_w, B_w, 0);
    // GEMM2 split-K: BMp + CMp (A = sum of XDBLp at load)
    gemm_splitk<<<dim3(12, 12, 3), 256>>>(x, B_w, C_w, 1);
    // Combine parts + conv + silu + softplus + pack
    fuse_kernel<<<dim3(24, 2), 384>>>(x, dt_b, conv_w, conv_b, Dvec);
    // Scan
    scan_kernel<<<384, 384>>>(A_log, out);
}